// round 1
// baseline (speedup 1.0000x reference)
#include <cuda_runtime.h>
#include <math.h>

#define B_    64
#define T_    1000
#define D_    512
#define V_    29
#define L_    200
#define S_    401            // 2*L + 1
#define CBLANK 28
#define NEGV  (-1e9f)

// ---------------- device scratch (no allocations allowed) ----------------
__device__ float d_lp[(long)B_ * T_ * V_];   // log_probs [b][t][v], 7.4 MB
__device__ float d_loss[B_];

// =====================================================================
// Kernel 1: logits = F @ W + b, then log_softmax over V, write d_lp.
// M=64000, K=512, N=29 (padded to 32). 128 threads, 128 rows per block,
// thread tile 8 rows x 4 cols.
// =====================================================================
#define BM      128
#define KC      32
#define FSTRIDE 132           // 128 + 4: keeps float4 alignment, tames conflicts

__global__ __launch_bounds__(128) void gemm_lsm_kernel(
    const float* __restrict__ F, const float* __restrict__ W,
    const float* __restrict__ bias)
{
    __shared__ float fbuf[KC * FSTRIDE];   // 4224 floats; reused as logits [128][33]
    __shared__ float wbuf[KC * 32];
    __shared__ float csh[BM];              // per-row (max + log(sumexp))

    const int tid  = threadIdx.x;
    const long rowBase = (long)blockIdx.x * BM;
    const float* Fb = F + rowBase * D_;

    const int cg   = tid & 7;        // col group 0..7
    const int rg   = tid >> 3;       // row group 0..15
    const int col0 = cg * 4;
    const int row0 = rg * 8;

    float acc[8][4];
#pragma unroll
    for (int i = 0; i < 8; i++)
#pragma unroll
        for (int j = 0; j < 4; j++) acc[i][j] = 0.f;

    for (int kc = 0; kc < D_; kc += KC) {
        // ---- load W chunk [KC][32], zero-pad v>=29 (coalesced) ----
        for (int i = tid; i < KC * 32; i += 128) {
            int k = i >> 5, v = i & 31;
            wbuf[i] = (v < V_) ? W[(long)(kc + k) * V_ + v] : 0.f;
        }
        // ---- load F chunk transposed into fbuf[k][row] ----
        {
            const int kk = (tid & 7) * 4;
            for (int r = (tid >> 3); r < BM; r += 16) {
                float4 v = *reinterpret_cast<const float4*>(Fb + (long)r * D_ + kc + kk);
                fbuf[(kk + 0) * FSTRIDE + r] = v.x;
                fbuf[(kk + 1) * FSTRIDE + r] = v.y;
                fbuf[(kk + 2) * FSTRIDE + r] = v.z;
                fbuf[(kk + 3) * FSTRIDE + r] = v.w;
            }
        }
        __syncthreads();

#pragma unroll
        for (int k = 0; k < KC; k++) {
            const float4 wv = *reinterpret_cast<const float4*>(&wbuf[k * 32 + col0]);
            const float4 f0 = *reinterpret_cast<const float4*>(&fbuf[k * FSTRIDE + row0]);
            const float4 f1 = *reinterpret_cast<const float4*>(&fbuf[k * FSTRIDE + row0 + 4]);
            const float fr[8] = {f0.x, f0.y, f0.z, f0.w, f1.x, f1.y, f1.z, f1.w};
            const float wr[4] = {wv.x, wv.y, wv.z, wv.w};
#pragma unroll
            for (int i = 0; i < 8; i++)
#pragma unroll
                for (int j = 0; j < 4; j++)
                    acc[i][j] = fmaf(fr[i], wr[j], acc[i][j]);
        }
        __syncthreads();
    }

    // ---- epilogue: bias, stash logits in fbuf as [row][33] ----
    float bv[4];
#pragma unroll
    for (int j = 0; j < 4; j++) bv[j] = (col0 + j < V_) ? bias[col0 + j] : 0.f;
#pragma unroll
    for (int i = 0; i < 8; i++)
#pragma unroll
        for (int j = 0; j < 4; j++)
            fbuf[(row0 + i) * 33 + col0 + j] = acc[i][j] + bv[j];
    __syncthreads();

    // per-row logsumexp (thread tid <-> row tid); bank-conflict-free (stride 33)
    {
        const float* r = &fbuf[tid * 33];
        float m = r[0];
#pragma unroll
        for (int v = 1; v < V_; v++) m = fmaxf(m, r[v]);
        float s = 0.f;
#pragma unroll
        for (int v = 0; v < V_; v++) s += __expf(r[v] - m);
        csh[tid] = m + __logf(s);
    }
    __syncthreads();

    // coalesced write of log_probs
    float* outp = d_lp + rowBase * V_;
    for (int i = tid; i < BM * V_; i += 128) {
        int row = i / V_;
        int v   = i - row * V_;
        outp[i] = fbuf[row * 33 + v] - csh[row];
    }
}

// =====================================================================
// Kernel 2: CTC alpha recursion. One block per batch element.
// 416 threads; thread s owns state s (s < 401). Double-buffered alpha in
// shared, ONE barrier per timestep. lp row prefetched 2 steps ahead.
// =====================================================================
__global__ __launch_bounds__(416) void ctc_kernel(
    const int* __restrict__ labels, const int* __restrict__ flens,
    const int* __restrict__ llens)
{
    __shared__ float abuf[2][S_ + 2];   // +2 front pad = NEG (for s-1, s-2)
    __shared__ float lpbuf[4][32];      // 4-deep ring of per-t log-prob rows
    __shared__ int   lab_sh[L_];

    const int b   = blockIdx.x;
    const int tid = threadIdx.x;
    const int flen = flens[b];
    const int llen = llens[b];

    for (int i = tid; i < L_; i += blockDim.x) lab_sh[i] = labels[b * L_ + i];
    if (tid < 2) { abuf[0][tid] = NEGV; abuf[1][tid] = NEGV; }
    __syncthreads();

    const int s = tid;
    int  ext  = CBLANK;
    bool skip = false;
    if (s < S_ && (s & 1)) {
        int j = s >> 1;
        ext  = lab_sh[j];
        skip = (s >= 3) ? (ext != lab_sh[j - 1]) : true;
    }

    const float* lpb = d_lp + (long)b * T_ * V_;

    // t = 0 init
    if (s < S_) {
        float a = NEGV;
        if (s == 0) a = lpb[CBLANK];
        else if (s == 1) a = lpb[ext];
        abuf[0][s + 2] = a;
    }

    // preload lp rows for t=1,2 into smem; t=3,4 into regs (2-ahead pipeline)
    float pf_odd = 0.f, pf_even = 0.f;   // pf_odd holds odd t, pf_even even t
    if (tid < V_) {
        lpbuf[1][tid] = lpb[1 * V_ + tid];
        lpbuf[2][tid] = lpb[2 * V_ + tid];
        pf_odd  = lpb[3 * V_ + tid];
        pf_even = lpb[4 * V_ + tid];
    }
    __syncthreads();

    int cur = 0;
    for (int t = 1; t < flen; t++) {
        // stage lp(t+2) from reg into ring slot; issue load of lp(t+4)
        if (tid < V_) {
            const int slot = (t + 2) & 3;
            const long nidx = (long)min(t + 4, T_ - 1) * V_ + tid;
            if (t & 1) { lpbuf[slot][tid] = pf_odd;  pf_odd  = lpb[nidx]; }
            else       { lpbuf[slot][tid] = pf_even; pf_even = lpb[nidx]; }
        }

        float na = NEGV;
        if (s < S_) {
            const float a0 = abuf[cur][s + 2];
            const float a1 = abuf[cur][s + 1];
            const float a2 = skip ? abuf[cur][s] : NEGV;
            const float m  = fmaxf(fmaxf(a0, a1), a2);
            const float sm = __expf(a0 - m) + __expf(a1 - m) + __expf(a2 - m);
            na = lpbuf[t & 3][ext] + m + __logf(sm);
            abuf[cur ^ 1][s + 2] = na;
        }
        cur ^= 1;
        __syncthreads();
    }

    if (tid == 0) {
        const float l1 = abuf[cur][2 * llen + 2];       // alpha[2*llen]
        const float l2 = abuf[cur][2 * llen + 1];       // alpha[2*llen - 1]
        const float m  = fmaxf(l1, l2);
        const float nll = -(m + __logf(__expf(l1 - m) + __expf(l2 - m)));
        d_loss[b] = (nll < 5e8f) ? nll / (float)llen : 0.f;
    }
}

// =====================================================================
// Kernel 3: deterministic fixed-order mean of 64 losses
// =====================================================================
__global__ void reduce_kernel(float* __restrict__ out)
{
    const int lane = threadIdx.x;
    float v = d_loss[lane] + d_loss[lane + 32];
#pragma unroll
    for (int o = 16; o > 0; o >>= 1) v += __shfl_down_sync(0xffffffffu, v, o);
    if (lane == 0) out[0] = v * (1.f / (float)B_);
}

// =====================================================================
extern "C" void kernel_launch(void* const* d_in, const int* in_sizes, int n_in,
                              void* d_out, int out_size)
{
    (void)in_sizes; (void)n_in; (void)out_size;
    const float* F     = (const float*)d_in[0];
    const float* W     = (const float*)d_in[1];
    const float* bias  = (const float*)d_in[2];
    const int*   labels = (const int*)d_in[3];
    const int*   flens  = (const int*)d_in[4];
    const int*   llens  = (const int*)d_in[5];
    float* out = (float*)d_out;

    gemm_lsm_kernel<<<(B_ * T_) / BM, 128>>>(F, W, bias);
    ctc_kernel<<<B_, 416>>>(labels, flens, llens);
    reduce_kernel<<<1, 32>>>(out);
}

// round 3
// speedup vs baseline: 1.5060x; 1.5060x over previous
#include <cuda_runtime.h>
#include <math.h>

#define B_    64
#define T_    1000
#define D_    512
#define V_    29
#define L_    200
#define S_    401            // 2*L + 1
#define CBLANK 28
#define NEGV  (-1e9f)
#define LOG2E 1.44269504088896340736f
#define LN2   0.69314718055994530942f

typedef unsigned long long u64;

// ---------------- device scratch (no allocations allowed) ----------------
__device__ float d_lp[(long)B_ * T_ * V_];   // LOG2-probs lp2[b][t][v], 7.4 MB
__device__ float d_loss[B_];

__device__ __forceinline__ float ex2f(float x){ float r; asm("ex2.approx.f32 %0, %1;" : "=f"(r) : "f"(x)); return r; }
__device__ __forceinline__ float lg2f(float x){ float r; asm("lg2.approx.f32 %0, %1;" : "=f"(r) : "f"(x)); return r; }

// =====================================================================
// Kernel 1: logits = F @ W + b, log2_softmax over V, write d_lp.
// M=64000, K=512, N=29 (padded 32). 128 threads, 128 rows/block,
// thread tile 8 rows x 4 cols via packed fma.rn.f32x2.
// =====================================================================
#define BM      128
#define KC      32
#define FSTRIDE 132

#define FMA2(d, a, b) asm("fma.rn.f32x2 %0, %1, %2, %0;" : "+l"(d) : "l"(a), "l"(b))

__global__ __launch_bounds__(128) void gemm_lsm_kernel(
    const float* __restrict__ F, const float* __restrict__ W,
    const float* __restrict__ bias)
{
    __shared__ float fbuf[KC * FSTRIDE];   // 4224 floats; reused as logits [128][33]
    __shared__ float wdup[KC * 32 * 2];    // duplicated (w,w) pairs
    __shared__ float csh[BM];              // per-row (max + log(sumexp))

    const int tid  = threadIdx.x;
    const long rowBase = (long)blockIdx.x * BM;
    const float* Fb = F + rowBase * D_;

    const int cg   = tid & 7;
    const int rg   = tid >> 3;
    const int col0 = cg * 4;
    const int row0 = rg * 8;

    u64 acc[4][4];
#pragma unroll
    for (int p = 0; p < 4; p++)
#pragma unroll
        for (int j = 0; j < 4; j++) acc[p][j] = 0ull;

    for (int kc = 0; kc < D_; kc += KC) {
        for (int i = tid; i < KC * 32; i += 128) {
            int k = i >> 5, v = i & 31;
            float w = (v < V_) ? W[(long)(kc + k) * V_ + v] : 0.f;
            wdup[2 * i] = w; wdup[2 * i + 1] = w;
        }
        {
            const int kk = (tid & 7) * 4;
            for (int r = (tid >> 3); r < BM; r += 16) {
                float4 v = *reinterpret_cast<const float4*>(Fb + (long)r * D_ + kc + kk);
                fbuf[(kk + 0) * FSTRIDE + r] = v.x;
                fbuf[(kk + 1) * FSTRIDE + r] = v.y;
                fbuf[(kk + 2) * FSTRIDE + r] = v.z;
                fbuf[(kk + 3) * FSTRIDE + r] = v.w;
            }
        }
        __syncthreads();

#pragma unroll
        for (int k = 0; k < KC; k++) {
            const ulonglong2* fp = reinterpret_cast<const ulonglong2*>(&fbuf[k * FSTRIDE + row0]);
            const ulonglong2 fa = fp[0], fb2 = fp[1];
            const ulonglong2* wp = reinterpret_cast<const ulonglong2*>(&wdup[(k * 32 + col0) * 2]);
            const ulonglong2 wa = wp[0], wb2 = wp[1];
            const u64 fr[4] = {fa.x, fa.y, fb2.x, fb2.y};
            const u64 wr[4] = {wa.x, wa.y, wb2.x, wb2.y};
#pragma unroll
            for (int p = 0; p < 4; p++)
#pragma unroll
                for (int j = 0; j < 4; j++)
                    FMA2(acc[p][j], fr[p], wr[j]);
        }
        __syncthreads();
    }

    float bv[4];
#pragma unroll
    for (int j = 0; j < 4; j++) bv[j] = (col0 + j < V_) ? bias[col0 + j] : 0.f;
#pragma unroll
    for (int p = 0; p < 4; p++)
#pragma unroll
        for (int j = 0; j < 4; j++) {
            float lo = __uint_as_float((unsigned)(acc[p][j] & 0xffffffffull));
            float hi = __uint_as_float((unsigned)(acc[p][j] >> 32));
            fbuf[(row0 + 2 * p    ) * 33 + col0 + j] = lo + bv[j];
            fbuf[(row0 + 2 * p + 1) * 33 + col0 + j] = hi + bv[j];
        }
    __syncthreads();

    // per-row (max + log(sumexp)); thread <-> row
    {
        const float* r = &fbuf[tid * 33];
        float m = r[0];
#pragma unroll
        for (int v = 1; v < V_; v++) m = fmaxf(m, r[v]);
        float sum = 0.f;
#pragma unroll
        for (int v = 0; v < V_; v++) sum += ex2f((r[v] - m) * LOG2E);
        csh[tid] = m + lg2f(sum) * LN2;
    }
    __syncthreads();

    // coalesced write of LOG2-probs
    float* outp = d_lp + rowBase * V_;
    for (int i = tid; i < BM * V_; i += 128) {
        int row = i / V_;
        int v   = i - row * V_;
        outp[i] = (fbuf[row * 33 + v] - csh[row]) * LOG2E;
    }
}

// =====================================================================
// Kernel 2: CTC alpha recursion, LOG2 domain. One block per batch.
// 416 threads, thread s owns state s; own alpha in a register;
// branch-free inner loop (padded abuf, warp-uniform prefetch);
// 3-MUFU logsumexp via exact median3. One barrier per step.
// =====================================================================
__global__ __launch_bounds__(416) void ctc_kernel(
    const int* __restrict__ labels, const int* __restrict__ flens,
    const int* __restrict__ llens)
{
    __shared__ float abuf[2][424];      // idx = state + 2; pads NEGV
    __shared__ float lpbuf[4][32];      // 4-deep ring of per-t log2-prob rows
    __shared__ int   lab_sh[L_];

    const int b    = blockIdx.x;
    const int tid  = threadIdx.x;
    const int flen = flens[b];
    const int llen = llens[b];

    for (int i = tid; i < L_; i += 416) lab_sh[i] = labels[b * L_ + i];
    for (int i = tid; i < 424; i += 416) { abuf[0][i] = NEGV; abuf[1][i] = NEGV; }
    __syncthreads();

    const int s = tid;                  // states 0..415 (401..415 = dummy lanes)
    int   ext  = CBLANK;
    bool  skip = false;
    if (s < S_ && (s & 1)) {
        int j = s >> 1;
        ext  = lab_sh[j];
        skip = (s >= 3) ? (ext != lab_sh[j - 1]) : true;
    }

    const float* lpb = d_lp + (long)b * T_ * V_;

    // t = 0 init (own alpha in register myA)
    float myA = NEGV;
    if (s < 2) myA = lpb[s == 0 ? CBLANK : ext];
    abuf[0][s + 2] = myA;

    // prefetch rows 1..2 -> smem ring; rows 3..4 -> regs (warp 0, uniform)
    const int vv = (tid < V_) ? tid : (V_ - 1);   // lanes 29..31 clamp (cols never read)
    float pf_odd = 0.f, pf_even = 0.f;
    if (tid < 32) {
        lpbuf[1][tid] = lpb[1 * V_ + vv];
        lpbuf[2][tid] = lpb[2 * V_ + vv];
        pf_odd  = lpb[3 * V_ + vv];
        pf_even = lpb[4 * V_ + vv];
    }
    __syncthreads();

    int cur = 0;
    for (int t = 1; t < flen; t++) {
        if (tid < 32) {                       // warp-uniform: no divergence
            const int slot = (t + 2) & 3;
            const long nidx = (long)min(t + 4, T_ - 1) * V_ + vv;
            if (t & 1) { lpbuf[slot][tid] = pf_odd;  pf_odd  = lpb[nidx]; }
            else       { lpbuf[slot][tid] = pf_even; pf_even = lpb[nidx]; }
        }
        const float a0  = myA;                       // own state (reg)
        const float a1  = abuf[cur][s + 1];          // state s-1
        const float a2r = abuf[cur][s];              // state s-2
        const float a2  = skip ? a2r : NEGV;
        // exact 3-way sort via selects (no cancellation)
        const float mab = fmaxf(a0, a1);
        const float nab = fminf(a0, a1);
        const float mx  = fmaxf(mab, a2);
        const float mn  = fminf(nab, a2);
        const float md  = fmaxf(nab, fminf(mab, a2));
        const float sm  = 1.0f + ex2f(mn - mx) + ex2f(md - mx);
        myA = lpbuf[t & 3][ext] + mx + lg2f(sm);
        abuf[cur ^ 1][s + 2] = myA;
        cur ^= 1;
        __syncthreads();
    }

    if (tid == 0) {
        const float l1 = abuf[cur][2 * llen + 2];    // alpha[2*llen]
        const float l2 = abuf[cur][2 * llen + 1];    // alpha[2*llen - 1]
        const float mx = fmaxf(l1, l2), mn = fminf(l1, l2);
        const float ls = mx + lg2f(1.0f + ex2f(mn - mx));
        const float nll = -ls * LN2;
        d_loss[b] = (nll < 5e8f) ? nll / (float)llen : 0.f;
    }
}

// =====================================================================
// Kernel 3: deterministic fixed-order mean of 64 losses
// =====================================================================
__global__ void reduce_kernel(float* __restrict__ out)
{
    const int lane = threadIdx.x;
    float v = d_loss[lane] + d_loss[lane + 32];
#pragma unroll
    for (int o = 16; o > 0; o >>= 1) v += __shfl_down_sync(0xffffffffu, v, o);
    if (lane == 0) out[0] = v * (1.f / (float)B_);
}

// =====================================================================
extern "C" void kernel_launch(void* const* d_in, const int* in_sizes, int n_in,
                              void* d_out, int out_size)
{
    (void)in_sizes; (void)n_in; (void)out_size;
    const float* F      = (const float*)d_in[0];
    const float* W      = (const float*)d_in[1];
    const float* bias   = (const float*)d_in[2];
    const int*   labels = (const int*)d_in[3];
    const int*   flens  = (const int*)d_in[4];
    const int*   llens  = (const int*)d_in[5];
    float* out = (float*)d_out;

    gemm_lsm_kernel<<<(B_ * T_) / BM, 128>>>(F, W, bias);
    ctc_kernel<<<B_, 416>>>(labels, flens, llens);
    reduce_kernel<<<1, 32>>>(out);
}